// round 1
// baseline (speedup 1.0000x reference)
#include <cuda_runtime.h>

#define N_NODES 100000
#define DIM 64
#define N_EDGES 1250000

// Scratch: per-node incoming-edge count (fp32 so finalize divides directly).
__device__ float g_cnt[N_NODES];

// Zero d_out (used as the sum accumulator) and g_cnt.
__global__ void zero_kernel(float* __restrict__ out) {
    int i = blockIdx.x * blockDim.x + threadIdx.x;
    if (i < (N_NODES * DIM) / 4) {
        float4 z = make_float4(0.f, 0.f, 0.f, 0.f);
        reinterpret_cast<float4*>(out)[i] = z;
    }
    if (i < N_NODES) g_cnt[i] = 0.f;
}

// One warp per edge: gather x[src] (64 floats, float2 per lane, coalesced 256B),
// scatter-add into out[dst]. Lane 0 bumps the count.
__global__ void scatter_kernel(const float* __restrict__ x,
                               const int* __restrict__ edge_index,
                               float* __restrict__ out) {
    int gtid = blockIdx.x * blockDim.x + threadIdx.x;
    int e = gtid >> 5;
    int lane = gtid & 31;
    if (e >= N_EDGES) return;

    int src = edge_index[e];
    int dst = edge_index[N_EDGES + e];

    const float2* xs = reinterpret_cast<const float2*>(x + (size_t)src * DIM);
    float2 v = xs[lane];

    float* o = out + (size_t)dst * DIM + lane * 2;
    atomicAdd(o, v.x);
    atomicAdd(o + 1, v.y);
    if (lane == 0) atomicAdd(&g_cnt[dst], 1.0f);
}

// One warp per node: mean = sum / max(cnt,1); h = mean/max(||mean||,eps);
// out = relu(2h). In-place on d_out.
__global__ void finalize_kernel(float* __restrict__ out) {
    int gtid = blockIdx.x * blockDim.x + threadIdx.x;
    int node = gtid >> 5;
    int lane = gtid & 31;
    if (node >= N_NODES) return;

    float inv_cnt = 1.0f / fmaxf(g_cnt[node], 1.0f);

    float2* o = reinterpret_cast<float2*>(out + (size_t)node * DIM);
    float2 v = o[lane];
    v.x *= inv_cnt;
    v.y *= inv_cnt;

    float ss = v.x * v.x + v.y * v.y;
    #pragma unroll
    for (int off = 16; off > 0; off >>= 1)
        ss += __shfl_xor_sync(0xFFFFFFFFu, ss, off);

    float norm = sqrtf(ss);
    float scale = 2.0f / fmaxf(norm, 1e-12f);

    v.x = fmaxf(v.x * scale, 0.0f);
    v.y = fmaxf(v.y * scale, 0.0f);
    o[lane] = v;
}

extern "C" void kernel_launch(void* const* d_in, const int* in_sizes, int n_in,
                              void* d_out, int out_size) {
    const float* x = (const float*)d_in[0];
    const int* edge_index = (const int*)d_in[1];
    // d_in[2] = edge_weights: unused by the reference computation.
    float* out = (float*)d_out;

    // Zero accumulators: covers max(N_NODES*DIM/4, N_NODES) = 1.6M threads.
    {
        int total = (N_NODES * DIM) / 4;  // 1,600,000 (> N_NODES)
        int threads = 256;
        int blocks = (total + threads - 1) / threads;
        zero_kernel<<<blocks, threads>>>(out);
    }

    // Edge scatter: warp per edge.
    {
        long long total_threads = (long long)N_EDGES * 32;
        int threads = 256;
        int blocks = (int)((total_threads + threads - 1) / threads);
        scatter_kernel<<<blocks, threads>>>(x, edge_index, out);
    }

    // Node finalize: warp per node.
    {
        long long total_threads = (long long)N_NODES * 32;
        int threads = 256;
        int blocks = (int)((total_threads + threads - 1) / threads);
        finalize_kernel<<<blocks, threads>>>(out);
    }
}

// round 3
// speedup vs baseline: 2.3573x; 2.3573x over previous
#include <cuda_runtime.h>

#define N_NODES 100000
#define DIM 64
#define N_EDGES 1250000
#define CAP 64          // bucket slots per node; Poisson(12.5) max degree ~40

// Static scratch (no runtime allocation).
__device__ int g_cnt[N_NODES];                 // incoming-edge count per node
__device__ int g_bucket[(size_t)N_NODES * CAP]; // src ids, bucketed by dst
__device__ int g_novf;                         // overflow edge count (normally 0)
__device__ int g_ovf_src[N_EDGES];             // overflow edges (correctness path)
__device__ int g_ovf_dst[N_EDGES];

__global__ void zero_kernel() {
    int i = blockIdx.x * blockDim.x + threadIdx.x;
    if (i < N_NODES) g_cnt[i] = 0;
    if (i == 0) g_novf = 0;
}

// Thread per edge: claim a slot in dst's bucket, store src.
__global__ void fill_kernel(const int* __restrict__ edge_index) {
    int e = blockIdx.x * blockDim.x + threadIdx.x;
    if (e >= N_EDGES) return;
    int src = edge_index[e];
    int dst = edge_index[N_EDGES + e];
    int slot = atomicAdd(&g_cnt[dst], 1);
    if (slot < CAP) {
        g_bucket[(size_t)dst * CAP + slot] = src;
    } else {
        int k = atomicAdd(&g_novf, 1);
        if (k < N_EDGES) { g_ovf_src[k] = src; g_ovf_dst[k] = dst; }
    }
}

// Warp per node: gather incoming rows, accumulate, mean + normalize + relu.
__global__ void pull_kernel(const float* __restrict__ x,
                            float* __restrict__ out) {
    int gtid = blockIdx.x * blockDim.x + threadIdx.x;
    int node = gtid >> 5;
    int lane = gtid & 31;
    if (node >= N_NODES) return;

    const unsigned FULL = 0xFFFFFFFFu;
    int cnt = g_cnt[node];
    int m = cnt < CAP ? cnt : CAP;

    float accx = 0.f, accy = 0.f;
    size_t base = (size_t)node * CAP;

    for (int i = 0; i < m; i += 32) {
        int s = 0;
        if (i + lane < m) s = g_bucket[base + i + lane];
        int n = (m - i) < 32 ? (m - i) : 32;
        for (int j = 0; j < n; j++) {
            int sj = __shfl_sync(FULL, s, j);
            float2 v = reinterpret_cast<const float2*>(x + (size_t)sj * DIM)[lane];
            accx += v.x;
            accy += v.y;
        }
    }

    // Overflow correctness path (normally dead: g_novf == 0).
    if (cnt > CAP) {
        int no = g_novf;
        if (no > N_EDGES) no = N_EDGES;
        for (int i = 0; i < no; i += 32) {
            int d = -1, s = 0;
            if (i + lane < no) { d = g_ovf_dst[i + lane]; s = g_ovf_src[i + lane]; }
            unsigned mask = __ballot_sync(FULL, d == node);
            while (mask) {
                int j = __ffs(mask) - 1;
                mask &= mask - 1;
                int sj = __shfl_sync(FULL, s, j);
                float2 v = reinterpret_cast<const float2*>(x + (size_t)sj * DIM)[lane];
                accx += v.x;
                accy += v.y;
            }
        }
    }

    float inv_cnt = 1.0f / fmaxf((float)cnt, 1.0f);
    accx *= inv_cnt;
    accy *= inv_cnt;

    float ss = accx * accx + accy * accy;
    #pragma unroll
    for (int off = 16; off > 0; off >>= 1)
        ss += __shfl_xor_sync(FULL, ss, off);

    float scale = 2.0f / fmaxf(sqrtf(ss), 1e-12f);
    float2 r;
    r.x = fmaxf(accx * scale, 0.0f);
    r.y = fmaxf(accy * scale, 0.0f);
    reinterpret_cast<float2*>(out + (size_t)node * DIM)[lane] = r;
}

extern "C" void kernel_launch(void* const* d_in, const int* in_sizes, int n_in,
                              void* d_out, int out_size) {
    const float* x = (const float*)d_in[0];
    const int* edge_index = (const int*)d_in[1];
    // d_in[2] = edge_weights: unused by the reference computation.
    float* out = (float*)d_out;

    {
        int threads = 256;
        int blocks = (N_NODES + threads - 1) / threads;
        zero_kernel<<<blocks, threads>>>();
    }
    {
        int threads = 256;
        int blocks = (N_EDGES + threads - 1) / threads;
        fill_kernel<<<blocks, threads>>>(edge_index);
    }
    {
        long long total = (long long)N_NODES * 32;
        int threads = 256;
        int blocks = (int)((total + threads - 1) / threads);
        pull_kernel<<<blocks, threads>>>(x, out);
    }
}